// round 2
// baseline (speedup 1.0000x reference)
#include <cuda_runtime.h>
#include <cuda_bf16.h>
#include <math.h>

#define Bb 8
#define Nb 300
#define Rr 36
#define Cc 256
#define PSORT 512
#define CONF_THR 0.3f
#define IOU_THR 0.7f

// scratch (allocation-free): selected boxes + packed (level<<1 | valid)
__device__ float4 g_selbox[Bb * Rr];
__device__ int    g_selinfo[Bb * Rr];

__global__ __launch_bounds__(PSORT)
void nms_kernel(const float* __restrict__ boxes, const float* __restrict__ scores)
{
    const int b   = blockIdx.x;
    const int tid = threadIdx.x;

    __shared__ unsigned long long key[PSORT];
    __shared__ float4 sb[Nb];
    __shared__ float  sarea[Nb];
    __shared__ int    skeep[Nb];

    // ---- build sort keys: descending score (thresholded), stable by index ----
    {
        unsigned long long k;
        if (tid < Nb) {
            float s  = scores[b * Nb + tid];
            float sv = (s > CONF_THR) ? s : -INFINITY;
            unsigned int bits = __float_as_uint(sv);
            unsigned int u = bits ^ ((bits >> 31) ? 0xFFFFFFFFu : 0x80000000u); // ascending-order map
            k = (((unsigned long long)(~u)) << 32) | (unsigned int)tid;         // descending s, asc idx
        } else {
            k = 0xFFFFFFFFFFFFFFFFull; // padding sorts last
        }
        key[tid] = k;
    }
    __syncthreads();

    // ---- bitonic sort ascending over PSORT elements ----
    for (int kk = 2; kk <= PSORT; kk <<= 1) {
        for (int j = kk >> 1; j > 0; j >>= 1) {
            int ixj = tid ^ j;
            if (ixj > tid) {
                bool up = ((tid & kk) == 0);
                unsigned long long a = key[tid], c = key[ixj];
                if ((a > c) == up) { key[tid] = c; key[ixj] = a; }
            }
            __syncthreads();
        }
    }

    // ---- gather sorted boxes, areas, initial keep ----
    if (tid < Nb) {
        int o = (int)(key[tid] & 0xFFFFFFFFu);
        const float* bp = boxes + ((size_t)b * Nb + o) * 4;
        float4 bx = make_float4(bp[0], bp[1], bp[2], bp[3]);
        sb[tid]    = bx;
        sarea[tid] = (bx.z - bx.x) * (bx.w - bx.y);
        float s    = scores[b * Nb + o];
        skeep[tid] = (s > CONF_THR) ? 1 : 0;
    }
    __syncthreads();

    // ---- greedy NMS: sequential over i, parallel over j ----
    for (int i = 0; i < Nb; i++) {
        if (skeep[i] && tid < Nb && tid > i && skeep[tid]) {
            float4 bi = sb[i];
            float4 bj = sb[tid];
            float ltx = fmaxf(bi.x, bj.x);
            float lty = fmaxf(bi.y, bj.y);
            float rbx = fminf(bi.z, bj.z);
            float rby = fminf(bi.w, bj.w);
            float w = fmaxf(rbx - ltx, 0.0f);
            float h = fmaxf(rby - lty, 0.0f);
            float inter = w * h;
            float iou = inter / (sarea[i] + sarea[tid] - inter + 1e-9f);
            if (iou > IOU_THR) skeep[tid] = 0;
        }
        __syncthreads();
    }

    // ---- stable partition (kept first), take first Rr, compute FPN level ----
    if (tid == 0) {
        int K = 0;
        for (int i = 0; i < Nb; i++) K += skeep[i];
        int ck = 0, cn = 0;
        for (int i = 0; i < Nb; i++) {
            int slot;
            if (skeep[i]) slot = ck++;
            else          slot = K + cn++;
            if (slot < Rr) {
                float4 bx = sb[i];
                g_selbox[b * Rr + slot] = bx;
                float dx = bx.z - bx.x;
                float dy = bx.w - bx.y;
                float size = sqrtf(fmaxf(dx * dx + dy * dy, 1e-12f));
                float t = floorf(4.0f + log2f(size / 224.0f * 4.0f));
                t = fminf(fmaxf(t, 2.0f), 5.0f);
                int lv = (int)t - 2;
                g_selinfo[b * Rr + slot] = (lv << 1) | skeep[i];
            }
        }
    }
}

__global__ __launch_bounds__(256)
void roi_kernel(const float* __restrict__ f0, const float* __restrict__ f1,
                const float* __restrict__ f2, const float* __restrict__ f3,
                float* __restrict__ out)
{
    const int rid = blockIdx.x;          // 0 .. B*R-1
    const int b   = rid / Rr;
    const int tid = threadIdx.x;
    float* o = out + (size_t)rid * Cc;

    const int info = g_selinfo[rid];
    if (!(info & 1)) {                   // invalid ROI -> zeros
        o[tid] = 0.0f;
        return;
    }

    const int lv = info >> 1;
    const float* feat;
    int H, W;
    if      (lv == 0) { feat = f0; H = 200; W = 200; }
    else if (lv == 1) { feat = f1; H = 100; W = 100; }
    else if (lv == 2) { feat = f2; H = 50;  W = 50;  }
    else              { feat = f3; H = 25;  W = 25;  }
    const size_t HW = (size_t)H * W;
    const float* fb = feat + (size_t)b * Cc * HW;

    const float4 bx = g_selbox[rid];
    const float rw = fmaxf(bx.z - bx.x, 1.0f);
    const float rh = fmaxf(bx.w - bx.y, 1.0f);

    __shared__ int4   soff[196];
    __shared__ float4 swts[196];

    if (tid < 196) {
        int gy = tid / 14;
        int gx = tid - gy * 14;
        float Y = bx.y + rh * ((gy + 0.5f) / 14.0f);
        float X = bx.x + rw * ((gx + 0.5f) / 14.0f);
        float Hf = (float)H, Wf = (float)W;
        bool oob = (Y < -1.0f) || (Y > Hf) || (X < -1.0f) || (X > Wf);
        float y = fminf(fmaxf(Y, 0.0f), Hf - 1.0f);
        float x = fminf(fmaxf(X, 0.0f), Wf - 1.0f);
        int y0 = (int)floorf(y);
        int x0 = (int)floorf(x);
        int y1i = min(y0 + 1, H - 1);
        int x1i = min(x0 + 1, W - 1);
        float ly = y - (float)y0;
        float lx = x - (float)x0;
        float w00 = (1.0f - ly) * (1.0f - lx);
        float w01 = (1.0f - ly) * lx;
        float w10 = ly * (1.0f - lx);
        float w11 = ly * lx;
        if (oob) {
            w00 = w01 = w10 = w11 = 0.0f;
            soff[tid] = make_int4(0, 0, 0, 0);
        } else {
            soff[tid] = make_int4(y0 * W + x0, y0 * W + x1i, y1i * W + x0, y1i * W + x1i);
        }
        swts[tid] = make_float4(w00, w01, w10, w11);
    }
    __syncthreads();

    const int warp = tid >> 5;
    const int lane = tid & 31;

    // each warp handles 32 consecutive channels
    for (int cc = 0; cc < 32; cc++) {
        const int c = warp * 32 + cc;
        const float* f = fb + (size_t)c * HW;
        float sum = 0.0f;
        #pragma unroll 7
        for (int p = lane; p < 196; p += 32) {
            int4   oo = soff[p];
            float4 w  = swts[p];
            sum += f[oo.x] * w.x + f[oo.y] * w.y + f[oo.z] * w.z + f[oo.w] * w.w;
        }
        #pragma unroll
        for (int s = 16; s; s >>= 1) sum += __shfl_down_sync(0xFFFFFFFFu, sum, s);
        if (lane == 0) o[c] = sum * (1.0f / 196.0f);
    }
}

extern "C" void kernel_launch(void* const* d_in, const int* in_sizes, int n_in,
                              void* d_out, int out_size)
{
    const float* boxes  = (const float*)d_in[0]; // (B,N,4)
    const float* scores = (const float*)d_in[1]; // (B,N)
    const float* f0     = (const float*)d_in[2]; // (B,C,200,200)
    const float* f1     = (const float*)d_in[3]; // (B,C,100,100)
    const float* f2     = (const float*)d_in[4]; // (B,C,50,50)
    const float* f3     = (const float*)d_in[5]; // (B,C,25,25)
    float* out          = (float*)d_out;         // (B,R,C)

    nms_kernel<<<Bb, PSORT>>>(boxes, scores);
    roi_kernel<<<Bb * Rr, 256>>>(f0, f1, f2, f3, out);
}

// round 5
// speedup vs baseline: 1.4156x; 1.4156x over previous
#include <cuda_runtime.h>
#include <cuda_bf16.h>
#include <math.h>

#define Bb 8
#define Nb 300
#define Rr 36
#define Cc 256
#define PSORT 512
#define CONF_THR 0.3f
#define IOU_THR 0.7f

#define CG 8          // channel groups per ROI
#define CPB 32        // channels per block (Cc / CG)

// scratch (allocation-free): selected boxes + packed (level<<1 | valid)
__device__ float4 g_selbox[Bb * Rr];
__device__ int    g_selinfo[Bb * Rr];

__global__ __launch_bounds__(PSORT)
void nms_kernel(const float* __restrict__ boxes, const float* __restrict__ scores)
{
    const int b   = blockIdx.x;
    const int tid = threadIdx.x;

    __shared__ unsigned long long key[PSORT];
    __shared__ float4 sb[Nb];
    __shared__ float  sarea[Nb];
    __shared__ int    skeep[Nb];

    // ---- build sort keys: descending score (thresholded), stable by index ----
    {
        unsigned long long k;
        if (tid < Nb) {
            float s  = scores[b * Nb + tid];
            float sv = (s > CONF_THR) ? s : -INFINITY;
            unsigned int bits = __float_as_uint(sv);
            unsigned int u = bits ^ ((bits >> 31) ? 0xFFFFFFFFu : 0x80000000u);
            k = (((unsigned long long)(~u)) << 32) | (unsigned int)tid;
        } else {
            k = 0xFFFFFFFFFFFFFFFFull;
        }
        key[tid] = k;
    }
    __syncthreads();

    // ---- bitonic sort ascending over PSORT elements ----
    for (int kk = 2; kk <= PSORT; kk <<= 1) {
        for (int j = kk >> 1; j > 0; j >>= 1) {
            int ixj = tid ^ j;
            if (ixj > tid) {
                bool up = ((tid & kk) == 0);
                unsigned long long a = key[tid], c = key[ixj];
                if ((a > c) == up) { key[tid] = c; key[ixj] = a; }
            }
            __syncthreads();
        }
    }

    // ---- gather sorted boxes, areas, initial keep ----
    if (tid < Nb) {
        int o = (int)(key[tid] & 0xFFFFFFFFu);
        const float* bp = boxes + ((size_t)b * Nb + o) * 4;
        float4 bx = make_float4(bp[0], bp[1], bp[2], bp[3]);
        sb[tid]    = bx;
        sarea[tid] = (bx.z - bx.x) * (bx.w - bx.y);
        float s    = scores[b * Nb + o];
        skeep[tid] = (s > CONF_THR) ? 1 : 0;
    }
    __syncthreads();

    // ---- greedy NMS: sequential over i, parallel over j ----
    for (int i = 0; i < Nb; i++) {
        if (skeep[i] && tid < Nb && tid > i && skeep[tid]) {
            float4 bi = sb[i];
            float4 bj = sb[tid];
            float ltx = fmaxf(bi.x, bj.x);
            float lty = fmaxf(bi.y, bj.y);
            float rbx = fminf(bi.z, bj.z);
            float rby = fminf(bi.w, bj.w);
            float w = fmaxf(rbx - ltx, 0.0f);
            float h = fmaxf(rby - lty, 0.0f);
            float inter = w * h;
            float iou = inter / (sarea[i] + sarea[tid] - inter + 1e-9f);
            if (iou > IOU_THR) skeep[tid] = 0;
        }
        __syncthreads();
    }

    // ---- stable partition (kept first), take first Rr, compute FPN level ----
    if (tid == 0) {
        int K = 0;
        for (int i = 0; i < Nb; i++) K += skeep[i];
        int ck = 0, cn = 0;
        for (int i = 0; i < Nb; i++) {
            int slot;
            if (skeep[i]) slot = ck++;
            else          slot = K + cn++;
            if (slot < Rr) {
                float4 bx = sb[i];
                g_selbox[b * Rr + slot] = bx;
                float dx = bx.z - bx.x;
                float dy = bx.w - bx.y;
                float size = sqrtf(fmaxf(dx * dx + dy * dy, 1e-12f));
                float t = floorf(4.0f + log2f(size / 224.0f * 4.0f));
                t = fminf(fmaxf(t, 2.0f), 5.0f);
                int lv = (int)t - 2;
                g_selinfo[b * Rr + slot] = (lv << 1) | skeep[i];
            }
        }
    }
}

// grid: (CG, B*R). Each block: 256 threads = 8 warps, each warp does 4 channels
// of its 32-channel group, accumulating all 4 inside the point loop (16 LDGs
// in flight per iteration).
__global__ __launch_bounds__(256)
void roi_kernel(const float* __restrict__ f0, const float* __restrict__ f1,
                const float* __restrict__ f2, const float* __restrict__ f3,
                float* __restrict__ out)
{
    const int cg  = blockIdx.x;          // 0 .. CG-1
    const int rid = blockIdx.y;          // 0 .. B*R-1
    const int b   = rid / Rr;
    const int tid = threadIdx.x;
    float* o = out + (size_t)rid * Cc + cg * CPB;

    const int info = g_selinfo[rid];
    if (!(info & 1)) {                   // invalid ROI -> zeros
        if (tid < CPB) o[tid] = 0.0f;
        return;
    }

    const int lv = info >> 1;
    const float* feat;
    int H, W;
    if      (lv == 0) { feat = f0; H = 200; W = 200; }
    else if (lv == 1) { feat = f1; H = 100; W = 100; }
    else if (lv == 2) { feat = f2; H = 50;  W = 50;  }
    else              { feat = f3; H = 25;  W = 25;  }
    const size_t HW = (size_t)H * W;
    const float* fb = feat + ((size_t)b * Cc + cg * CPB) * HW;

    const float4 bx = g_selbox[rid];
    const float rw = fmaxf(bx.z - bx.x, 1.0f);
    const float rh = fmaxf(bx.w - bx.y, 1.0f);

    __shared__ int4   soff[196];
    __shared__ float4 swts[196];

    if (tid < 196) {
        int gy = tid / 14;
        int gx = tid - gy * 14;
        float Y = bx.y + rh * ((gy + 0.5f) / 14.0f);
        float X = bx.x + rw * ((gx + 0.5f) / 14.0f);
        float Hf = (float)H, Wf = (float)W;
        bool oob = (Y < -1.0f) || (Y > Hf) || (X < -1.0f) || (X > Wf);
        float y = fminf(fmaxf(Y, 0.0f), Hf - 1.0f);
        float x = fminf(fmaxf(X, 0.0f), Wf - 1.0f);
        int y0 = (int)floorf(y);
        int x0 = (int)floorf(x);
        int y1i = min(y0 + 1, H - 1);
        int x1i = min(x0 + 1, W - 1);
        float ly = y - (float)y0;
        float lx = x - (float)x0;
        float w00 = (1.0f - ly) * (1.0f - lx);
        float w01 = (1.0f - ly) * lx;
        float w10 = ly * (1.0f - lx);
        float w11 = ly * lx;
        if (oob) {
            w00 = w01 = w10 = w11 = 0.0f;
            soff[tid] = make_int4(0, 0, 0, 0);
        } else {
            soff[tid] = make_int4(y0 * W + x0, y0 * W + x1i, y1i * W + x0, y1i * W + x1i);
        }
        swts[tid] = make_float4(w00, w01, w10, w11);
    }
    __syncthreads();

    const int warp = tid >> 5;
    const int lane = tid & 31;

    // 4 channels per warp, all accumulated in the same point loop
    const int c0 = warp * 4;
    const float* fB = fb + (size_t)c0 * HW;

    float s0 = 0.0f, s1 = 0.0f, s2 = 0.0f, s3 = 0.0f;
    #pragma unroll 7
    for (int p = lane; p < 196; p += 32) {
        int4   oo = soff[p];
        float4 w  = swts[p];
        const float* fp0 = fB;
        const float* fp1 = fB + HW;
        const float* fp2 = fB + 2 * HW;
        const float* fp3 = fB + 3 * HW;
        s0 += fp0[oo.x] * w.x + fp0[oo.y] * w.y + fp0[oo.z] * w.z + fp0[oo.w] * w.w;
        s1 += fp1[oo.x] * w.x + fp1[oo.y] * w.y + fp1[oo.z] * w.z + fp1[oo.w] * w.w;
        s2 += fp2[oo.x] * w.x + fp2[oo.y] * w.y + fp2[oo.z] * w.z + fp2[oo.w] * w.w;
        s3 += fp3[oo.x] * w.x + fp3[oo.y] * w.y + fp3[oo.z] * w.z + fp3[oo.w] * w.w;
    }
    #pragma unroll
    for (int s = 16; s; s >>= 1) {
        s0 += __shfl_down_sync(0xFFFFFFFFu, s0, s);
        s1 += __shfl_down_sync(0xFFFFFFFFu, s1, s);
        s2 += __shfl_down_sync(0xFFFFFFFFu, s2, s);
        s3 += __shfl_down_sync(0xFFFFFFFFu, s3, s);
    }
    if (lane == 0) {
        o[c0 + 0] = s0 * (1.0f / 196.0f);
        o[c0 + 1] = s1 * (1.0f / 196.0f);
        o[c0 + 2] = s2 * (1.0f / 196.0f);
        o[c0 + 3] = s3 * (1.0f / 196.0f);
    }
}

extern "C" void kernel_launch(void* const* d_in, const int* in_sizes, int n_in,
                              void* d_out, int out_size)
{
    const float* boxes  = (const float*)d_in[0]; // (B,N,4)
    const float* scores = (const float*)d_in[1]; // (B,N)
    const float* f0     = (const float*)d_in[2]; // (B,C,200,200)
    const float* f1     = (const float*)d_in[3]; // (B,C,100,100)
    const float* f2     = (const float*)d_in[4]; // (B,C,50,50)
    const float* f3     = (const float*)d_in[5]; // (B,C,25,25)
    float* out          = (float*)d_out;         // (B,R,C)

    nms_kernel<<<Bb, PSORT>>>(boxes, scores);
    dim3 grid(CG, Bb * Rr);
    roi_kernel<<<grid, 256>>>(f0, f1, f2, f3, out);
}

// round 6
// speedup vs baseline: 1.9788x; 1.3978x over previous
#include <cuda_runtime.h>
#include <cuda_bf16.h>
#include <math.h>

#define Bb 8
#define Nb 300
#define Rr 36
#define Cc 256
#define PSORT 512
#define CONF_THR 0.3f
#define IOU_THR 0.7f
#define NW 10          // ceil(Nb/32) keep-mask words

#define CG 8           // channel groups per ROI
#define CPB 32         // channels per block (Cc / CG)

// scratch (allocation-free): selected boxes + packed (level<<1 | valid)
__device__ float4 g_selbox[Bb * Rr];
__device__ int    g_selinfo[Bb * Rr];

__global__ __launch_bounds__(PSORT)
void nms_kernel(const float* __restrict__ boxes, const float* __restrict__ scores)
{
    const int b   = blockIdx.x;
    const int tid = threadIdx.x;

    __shared__ unsigned long long key[PSORT];
    __shared__ float4       sb[Nb];
    __shared__ float        sarea[Nb];
    __shared__ unsigned int srow[Nb * NW];   // suppression bit-matrix (j>i only)
    __shared__ unsigned int validw[NW];
    __shared__ unsigned int keepw[NW];

    // ---- build sort keys: descending score (thresholded), stable by index ----
    {
        unsigned long long k;
        if (tid < Nb) {
            float s  = scores[b * Nb + tid];
            float sv = (s > CONF_THR) ? s : -INFINITY;
            unsigned int bits = __float_as_uint(sv);
            unsigned int u = bits ^ ((bits >> 31) ? 0xFFFFFFFFu : 0x80000000u);
            k = (((unsigned long long)(~u)) << 32) | (unsigned int)tid;
        } else {
            k = 0xFFFFFFFFFFFFFFFFull;
        }
        key[tid] = k;
    }
    if (tid < NW) validw[tid] = 0u;
    __syncthreads();

    // ---- bitonic sort ascending over PSORT elements ----
    for (int kk = 2; kk <= PSORT; kk <<= 1) {
        for (int j = kk >> 1; j > 0; j >>= 1) {
            int ixj = tid ^ j;
            if (ixj > tid) {
                bool up = ((tid & kk) == 0);
                unsigned long long a = key[tid], c = key[ixj];
                if ((a > c) == up) { key[tid] = c; key[ixj] = a; }
            }
            __syncthreads();
        }
    }

    // ---- gather sorted boxes, areas, initial validity bits ----
    if (tid < Nb) {
        int o = (int)(key[tid] & 0xFFFFFFFFu);
        const float* bp = boxes + ((size_t)b * Nb + o) * 4;
        float4 bx = make_float4(bp[0], bp[1], bp[2], bp[3]);
        sb[tid]    = bx;
        sarea[tid] = (bx.z - bx.x) * (bx.w - bx.y);
        float s    = scores[b * Nb + o];
        if (s > CONF_THR) atomicOr(&validw[tid >> 5], 1u << (tid & 31));
    }
    __syncthreads();

    // ---- build suppression bit matrix: bit j of word (i,w) set iff
    //      j>i and iou(i,j) > THR (upper triangle only) ----
    for (int t = tid; t < Nb * NW; t += PSORT) {
        int i = t / NW;
        int w = t - i * NW;
        unsigned int bits = 0u;
        int j0 = w << 5;
        if (j0 + 31 > i) {
            float4 bi = sb[i];
            float  ai = sarea[i];
            int jbeg = max(j0, i + 1);
            int jend = min(j0 + 32, Nb);
            for (int j = jbeg; j < jend; j++) {
                float4 bj = sb[j];
                float ltx = fmaxf(bi.x, bj.x);
                float lty = fmaxf(bi.y, bj.y);
                float rbx = fminf(bi.z, bj.z);
                float rby = fminf(bi.w, bj.w);
                float ww = fmaxf(rbx - ltx, 0.0f);
                float hh = fmaxf(rby - lty, 0.0f);
                float inter = ww * hh;
                float iou = inter / (ai + sarea[j] - inter + 1e-9f);
                if (iou > IOU_THR) bits |= 1u << (j - j0);
            }
        }
        srow[t] = bits;
    }
    __syncthreads();

    // ---- greedy suppression: single warp, no barriers.
    //      lane k owns keep word k; prefetch next row to hide LDS latency ----
    if (tid < 32) {
        unsigned int kw   = (tid < NW) ? validw[tid] : 0u;
        unsigned int nrow = (tid < NW) ? srow[tid]   : 0u;
        for (int i = 0; i < Nb; i++) {
            unsigned int row = nrow;
            if (tid < NW && i + 1 < Nb) nrow = srow[(i + 1) * NW + tid];
            unsigned int wi = __shfl_sync(0xFFFFFFFFu, kw, i >> 5);
            if ((wi >> (i & 31)) & 1u) kw &= ~row;
        }
        if (tid < NW) keepw[tid] = kw;
    }
    __syncthreads();

    // ---- parallel stable partition (kept first), take first Rr, FPN level ----
    if (tid < Nb) {
        int w   = tid >> 5;
        int bit = tid & 31;
        unsigned int myw = keepw[w];
        int kept = (myw >> bit) & 1;
        int kpre = __popc(myw & ((1u << bit) - 1u));
        for (int u = 0; u < w; u++) kpre += __popc(keepw[u]);
        int K = 0;
        #pragma unroll
        for (int u = 0; u < NW; u++) K += __popc(keepw[u]);
        int slot = kept ? kpre : (K + (tid - kpre));
        if (slot < Rr) {
            float4 bx = sb[tid];
            g_selbox[b * Rr + slot] = bx;
            float dx = bx.z - bx.x;
            float dy = bx.w - bx.y;
            float size = sqrtf(fmaxf(dx * dx + dy * dy, 1e-12f));
            float t = floorf(4.0f + log2f(size / 224.0f * 4.0f));
            t = fminf(fmaxf(t, 2.0f), 5.0f);
            int lv = (int)t - 2;
            g_selinfo[b * Rr + slot] = (lv << 1) | kept;
        }
    }
}

// grid: (CG, B*R). 256 threads = 8 warps; each warp does 4 channels.
// Point loop processes TWO grid points per iteration -> 32 LDGs in flight.
__global__ __launch_bounds__(256)
void roi_kernel(const float* __restrict__ f0, const float* __restrict__ f1,
                const float* __restrict__ f2, const float* __restrict__ f3,
                float* __restrict__ out)
{
    const int cg  = blockIdx.x;          // 0 .. CG-1
    const int rid = blockIdx.y;          // 0 .. B*R-1
    const int b   = rid / Rr;
    const int tid = threadIdx.x;
    float* o = out + (size_t)rid * Cc + cg * CPB;

    const int info = g_selinfo[rid];
    if (!(info & 1)) {                   // invalid ROI -> zeros
        if (tid < CPB) o[tid] = 0.0f;
        return;
    }

    const int lv = info >> 1;
    const float* feat;
    int H, W;
    if      (lv == 0) { feat = f0; H = 200; W = 200; }
    else if (lv == 1) { feat = f1; H = 100; W = 100; }
    else if (lv == 2) { feat = f2; H = 50;  W = 50;  }
    else              { feat = f3; H = 25;  W = 25;  }
    const int HW = H * W;
    const float* fb = feat + ((size_t)b * Cc + cg * CPB) * HW;

    const float4 bx = g_selbox[rid];
    const float rw = fmaxf(bx.z - bx.x, 1.0f);
    const float rh = fmaxf(bx.w - bx.y, 1.0f);

    __shared__ int4   soff[196];
    __shared__ float4 swts[196];

    if (tid < 196) {
        int gy = tid / 14;
        int gx = tid - gy * 14;
        float Y = bx.y + rh * ((gy + 0.5f) / 14.0f);
        float X = bx.x + rw * ((gx + 0.5f) / 14.0f);
        float Hf = (float)H, Wf = (float)W;
        bool oob = (Y < -1.0f) || (Y > Hf) || (X < -1.0f) || (X > Wf);
        float y = fminf(fmaxf(Y, 0.0f), Hf - 1.0f);
        float x = fminf(fmaxf(X, 0.0f), Wf - 1.0f);
        int y0 = (int)floorf(y);
        int x0 = (int)floorf(x);
        int y1i = min(y0 + 1, H - 1);
        int x1i = min(x0 + 1, W - 1);
        float ly = y - (float)y0;
        float lx = x - (float)x0;
        float w00 = (1.0f - ly) * (1.0f - lx);
        float w01 = (1.0f - ly) * lx;
        float w10 = ly * (1.0f - lx);
        float w11 = ly * lx;
        if (oob) {
            w00 = w01 = w10 = w11 = 0.0f;
            soff[tid] = make_int4(0, 0, 0, 0);
        } else {
            soff[tid] = make_int4(y0 * W + x0, y0 * W + x1i, y1i * W + x0, y1i * W + x1i);
        }
        swts[tid] = make_float4(w00, w01, w10, w11);
    }
    __syncthreads();

    const int warp = tid >> 5;
    const int lane = tid & 31;

    const int c0 = warp * 4;
    const float* fB = fb + (size_t)c0 * HW;

    float acc[4] = {0.0f, 0.0f, 0.0f, 0.0f};

    int p = lane;
    #pragma unroll 1
    for (; p + 32 < 196; p += 64) {
        int4   oa = soff[p];
        float4 wa = swts[p];
        int4   ob = soff[p + 32];
        float4 wb = swts[p + 32];
        float va[4][4], vb[4][4];
        #pragma unroll
        for (int c = 0; c < 4; c++) {
            const float* f = fB + c * HW;
            va[c][0] = f[oa.x]; va[c][1] = f[oa.y]; va[c][2] = f[oa.z]; va[c][3] = f[oa.w];
            vb[c][0] = f[ob.x]; vb[c][1] = f[ob.y]; vb[c][2] = f[ob.z]; vb[c][3] = f[ob.w];
        }
        #pragma unroll
        for (int c = 0; c < 4; c++) {
            acc[c] += va[c][0] * wa.x + va[c][1] * wa.y + va[c][2] * wa.z + va[c][3] * wa.w;
            acc[c] += vb[c][0] * wb.x + vb[c][1] * wb.y + vb[c][2] * wb.z + vb[c][3] * wb.w;
        }
    }
    if (p < 196) {   // tail point (lanes 0..3: p = lane + 192)
        int4   oa = soff[p];
        float4 wa = swts[p];
        #pragma unroll
        for (int c = 0; c < 4; c++) {
            const float* f = fB + c * HW;
            acc[c] += f[oa.x] * wa.x + f[oa.y] * wa.y + f[oa.z] * wa.z + f[oa.w] * wa.w;
        }
    }

    #pragma unroll
    for (int s = 16; s; s >>= 1) {
        acc[0] += __shfl_down_sync(0xFFFFFFFFu, acc[0], s);
        acc[1] += __shfl_down_sync(0xFFFFFFFFu, acc[1], s);
        acc[2] += __shfl_down_sync(0xFFFFFFFFu, acc[2], s);
        acc[3] += __shfl_down_sync(0xFFFFFFFFu, acc[3], s);
    }
    if (lane == 0) {
        o[c0 + 0] = acc[0] * (1.0f / 196.0f);
        o[c0 + 1] = acc[1] * (1.0f / 196.0f);
        o[c0 + 2] = acc[2] * (1.0f / 196.0f);
        o[c0 + 3] = acc[3] * (1.0f / 196.0f);
    }
}

extern "C" void kernel_launch(void* const* d_in, const int* in_sizes, int n_in,
                              void* d_out, int out_size)
{
    const float* boxes  = (const float*)d_in[0]; // (B,N,4)
    const float* scores = (const float*)d_in[1]; // (B,N)
    const float* f0     = (const float*)d_in[2]; // (B,C,200,200)
    const float* f1     = (const float*)d_in[3]; // (B,C,100,100)
    const float* f2     = (const float*)d_in[4]; // (B,C,50,50)
    const float* f3     = (const float*)d_in[5]; // (B,C,25,25)
    float* out          = (float*)d_out;         // (B,R,C)

    nms_kernel<<<Bb, PSORT>>>(boxes, scores);
    dim3 grid(CG, Bb * Rr);
    roi_kernel<<<grid, 256>>>(f0, f1, f2, f3, out);
}